// round 13
// baseline (speedup 1.0000x reference)
#include <cuda_runtime.h>
#include <cuda_bf16.h>
#include <stdint.h>
#include <float.h>
#include <math.h>

#define NN 50000
#define NE 400000
#define FIN 514
#define KPAD 544
#define HH 128
#define HB2 256
#define CO 4

#define SZ_W1  (HH*HB2)
#define SZ_W2  (HB2*HH)
#define OFF_W1 0
#define OFF_W2 (3*SZ_W1)
#define WTOT   (OFF_W2 + 3*SZ_W2)

// ---------------- scratch ----------------
__device__ __align__(256) float g_x0 [NN*HH];
__device__ __align__(256) float g_x  [NN*HH];
__device__ __align__(256) float g_y  [NN*HH];
__device__ __align__(256) float g_mid[NN*HB2];
__device__ __align__(256) __nv_bfloat16 g_aggh[NN*HH];
__device__ __align__(256) __nv_bfloat16 g_aggl[NN*HH];
__device__ __align__(256) __nv_bfloat16 g_midh[NN*HB2];
__device__ __align__(256) __nv_bfloat16 g_midl[NN*HB2];
__device__ __align__(256) __nv_bfloat16 g_bwh[WTOT];
__device__ __align__(256) __nv_bfloat16 g_bwl[WTOT];
__device__ __align__(256) __nv_bfloat16 g_wnh[KPAD*HH];
__device__ __align__(256) __nv_bfloat16 g_wnl[KPAD*HH];
__device__ __align__(256) __nv_bfloat16 g_xh[(size_t)NN*KPAD];
__device__ __align__(256) __nv_bfloat16 g_xl[(size_t)NN*KPAD];
__device__ int g_cnt[NN];
__device__ int g_off[NN+1];
__device__ int g_bsum[64];
__device__ unsigned g_wctr[4];
__device__ int g_psrc[NE];
__device__ __align__(256) float2 g_pear[NE];

// ---------------- helpers ----------------
__device__ __forceinline__ float wred(float v) {
#pragma unroll
    for (int o = 16; o > 0; o >>= 1) v += __shfl_xor_sync(0xffffffffu, v, o);
    return v;
}

__device__ __forceinline__ void mma_bf16(float c[4],
    unsigned a0, unsigned a1, unsigned a2, unsigned a3,
    unsigned b0, unsigned b1)
{
    asm volatile(
        "mma.sync.aligned.m16n8k16.row.col.f32.bf16.bf16.f32 "
        "{%0,%1,%2,%3}, {%4,%5,%6,%7}, {%8,%9}, {%0,%1,%2,%3};\n"
        : "+f"(c[0]), "+f"(c[1]), "+f"(c[2]), "+f"(c[3])
        : "r"(a0), "r"(a1), "r"(a2), "r"(a3), "r"(b0), "r"(b1));
}

__device__ __forceinline__ void ldsm_x4(unsigned& r0, unsigned& r1,
                                        unsigned& r2, unsigned& r3, unsigned addr)
{
    asm volatile("ldmatrix.sync.aligned.m8n8.x4.shared.b16 {%0,%1,%2,%3}, [%4];\n"
        : "=r"(r0), "=r"(r1), "=r"(r2), "=r"(r3) : "r"(addr));
}

__device__ __forceinline__ void ldsm_x4_t(unsigned& r0, unsigned& r1,
                                          unsigned& r2, unsigned& r3, unsigned addr)
{
    asm volatile("ldmatrix.sync.aligned.m8n8.x4.trans.shared.b16 {%0,%1,%2,%3}, [%4];\n"
        : "=r"(r0), "=r"(r1), "=r"(r2), "=r"(r3) : "r"(addr));
}

__device__ __forceinline__ void cp16(unsigned dst, const void* src) {
    asm volatile("cp.async.cg.shared.global [%0], [%1], 16;\n" :: "r"(dst), "l"(src));
}
__device__ __forceinline__ void cp_commit() {
    asm volatile("cp.async.commit_group;\n");
}
template<int Ngrp> __device__ __forceinline__ void cp_wait() {
    asm volatile("cp.async.wait_group %0;\n" :: "n"(Ngrp));
}

__device__ __forceinline__ void split2(float v, __nv_bfloat16& h, __nv_bfloat16& l) {
    h = __float2bfloat16_rn(v);
    l = __float2bfloat16_rn(v - __bfloat162float(h));
}

// ---------------- prep ----------------
#define PREP_Z0 (NN)
#define PREP_Z1 (PREP_Z0 + KPAD*HH)
#define PREP_Z2 (PREP_Z1 + 3*SZ_W1)
#define PREP_Z3 (PREP_Z2 + 3*SZ_W2)
#define XF2     (KPAD/2)
#define PREP_Z4 (PREP_Z3 + NN*XF2)

__global__ void k_prep(const float* __restrict__ Wn, const float* __restrict__ W1,
                       const float* __restrict__ W2, const float* __restrict__ X)
{
    int idx = blockIdx.x * blockDim.x + threadIdx.x;
    if (idx < PREP_Z0) { g_cnt[idx] = 0; return; }
    if (idx < PREP_Z1) {
        int j = idx - PREP_Z0;
        int r = j >> 7;
        int c = j & 127;
        float v = (r < FIN) ? Wn[r * HH + c] : 0.f;
        __nv_bfloat16 h, l; split2(v, h, l);
        g_wnh[j] = h; g_wnl[j] = l;
        return;
    }
    if (idx < PREP_Z2) {
        int j = idx - PREP_Z1;
        __nv_bfloat16 h, l; split2(W1[j], h, l);
        g_bwh[OFF_W1 + j] = h; g_bwl[OFF_W1 + j] = l;
        return;
    }
    if (idx < PREP_Z3) {
        int j = idx - PREP_Z2;
        __nv_bfloat16 h, l; split2(W2[j], h, l);
        g_bwh[OFF_W2 + j] = h; g_bwl[OFF_W2 + j] = l;
        return;
    }
    if (idx < PREP_Z4) {
        int j = idx - PREP_Z3;
        int row = j / XF2;
        int c2 = j - row * XF2;
        float2 v;
        if (c2 * 2 < FIN) v = *(const float2*)(X + (size_t)row * FIN + c2 * 2);
        else              v = make_float2(0.f, 0.f);
        __nv_bfloat16 h0, l0, h1, l1;
        split2(v.x, h0, l0); split2(v.y, h1, l1);
        size_t o = (size_t)row * KPAD + c2 * 2;
        *(__nv_bfloat162*)(g_xh + o) = __halves2bfloat162(h0, h1);
        *(__nv_bfloat162*)(g_xl + o) = __halves2bfloat162(l0, l1);
    }
}

// ---------------- CSR build ----------------
__global__ void k_hist(const int* __restrict__ dst) {
    int e = blockIdx.x * blockDim.x + threadIdx.x;
    if (e < NE) atomicAdd(&g_cnt[dst[e]], 1);
}

__global__ void __launch_bounds__(1024) k_scan1() {
    __shared__ int wsum[32];
    int tid = threadIdx.x;
    int i = blockIdx.x * 1024 + tid;
    int v = (i < NN) ? g_cnt[i] : 0;
    int x = v;
    int lane = tid & 31;
#pragma unroll
    for (int o = 1; o < 32; o <<= 1) {
        int t = __shfl_up_sync(0xffffffffu, x, o);
        if (lane >= o) x += t;
    }
    if (lane == 31) wsum[tid >> 5] = x;
    __syncthreads();
    if (tid < 32) {
        int orig = wsum[tid];
        int y = orig;
#pragma unroll
        for (int o = 1; o < 32; o <<= 1) {
            int t = __shfl_up_sync(0xffffffffu, y, o);
            if (tid >= o) y += t;
        }
        wsum[tid] = y - orig;
    }
    __syncthreads();
    int excl = x - v + wsum[tid >> 5];
    if (i < NN) g_off[i] = excl;
    if (tid == 1023) g_bsum[blockIdx.x] = excl + v;
}

__global__ void k_scan2() {
    __shared__ int s[64];
    int tid = threadIdx.x;
    if (tid < 4) g_wctr[tid] = 0u;
    int v = (tid < 49) ? g_bsum[tid] : 0;
    s[tid] = v;
    __syncthreads();
    for (int o = 1; o < 64; o <<= 1) {
        int t = (tid >= o) ? s[tid - o] : 0;
        __syncthreads();
        s[tid] += t;
        __syncthreads();
    }
    if (tid < 49) g_bsum[tid] = s[tid] - v;
    if (tid == 48) g_off[NN] = s[48];
}

__global__ void __launch_bounds__(1024) k_scan3() {
    int i = blockIdx.x * 1024 + threadIdx.x;
    if (i < NN) {
        int t = g_off[i] + g_bsum[blockIdx.x];
        g_off[i] = t;
        g_cnt[i] = t;
    }
}

__global__ void k_scatter(const int* __restrict__ src, const int* __restrict__ dst,
                          const float2* __restrict__ ear) {
    int e = blockIdx.x * blockDim.x + threadIdx.x;
    if (e >= NE) return;
    int d = dst[e];
    int pos = atomicAdd(&g_cnt[d], 1);
    g_psrc[pos] = src[e];
    g_pear[pos] = ear[e];
}

// ---------------- GEMM layout ----------------
#define APAD 40
#define BPAD 136
#define SOFF_AL (128*APAD)
#define SOFF_BH (2*128*APAD)
#define SOFF_BL (SOFF_BH + 32*BPAD)
#define STAGE_HW (SOFF_BL + 32*BPAD)
#define SMEM_PIPE_BYTES (2 * STAGE_HW * 2)

// ---------------- pipelined GEMM, tile 128x128, 256 threads ----------------
__global__ void __launch_bounds__(256) k_gemm_pipe(
    const __nv_bfloat16* __restrict__ Ah, const __nv_bfloat16* __restrict__ Al,
    const __nv_bfloat16* __restrict__ Bh, const __nv_bfloat16* __restrict__ Bl,
    const float* __restrict__ bias, const float* __restrict__ Res,
    float* __restrict__ Cc, int M, int K, int Nn,
    const float* __restrict__ png, const float* __restrict__ pnb,
    float* __restrict__ Yout)
{
    extern __shared__ __nv_bfloat16 smp[];
    const int tid = threadIdx.x;
    const int lane = tid & 31;
    const int wid = tid >> 5;
    const int wm = (wid & 3) << 5;
    const int wn = (wid >> 2) << 6;
    const int mBase = blockIdx.y << 7;
    const int nBase = blockIdx.x << 7;

    const int lr = lane & 7;
    const int sel = lane >> 3;
    const int selR = (sel & 1) << 3;
    const int selC = (sel >> 1) << 3;

    const unsigned sBase = (unsigned)__cvta_generic_to_shared(&smp[0]);

    const int arow = tid >> 1;
    const int acol = (tid & 1) << 4;
    const int brow = tid >> 3;
    const int bcol = (tid & 7) << 4;

    const int gmRaw = mBase + arow;
    const int gmCl = (gmRaw < M) ? gmRaw : (M - 1);
    const __nv_bfloat16* aSrcH = Ah + (size_t)gmCl * K + acol;
    const __nv_bfloat16* aSrcL = Al + (size_t)gmCl * K + acol;
    const __nv_bfloat16* bSrcH = Bh + (size_t)brow * Nn + nBase + bcol;
    const __nv_bfloat16* bSrcL = Bl + (size_t)brow * Nn + nBase + bcol;
    const size_t bStep = (size_t)32 * Nn;

    const unsigned aDst = sBase + (unsigned)((arow * APAD + acol) * 2);
    const unsigned bDst = sBase + (unsigned)((brow * BPAD + bcol) * 2);

    float Cacc[2][8][4];
#pragma unroll
    for (int i = 0; i < 2; i++)
#pragma unroll
        for (int j = 0; j < 8; j++)
#pragma unroll
            for (int q = 0; q < 4; q++) Cacc[i][j][q] = 0.f;

    const int nch = K >> 5;

    auto issue = [&](int c, int s) {
        unsigned so = (unsigned)(s * STAGE_HW * 2);
        int k0 = c << 5;
        cp16(aDst + so,                     aSrcH + (size_t)k0);
        cp16(aDst + so + 16,                aSrcH + (size_t)k0 + 8);
        cp16(aDst + so + SOFF_AL * 2,       aSrcL + (size_t)k0);
        cp16(aDst + so + SOFF_AL * 2 + 16,  aSrcL + (size_t)k0 + 8);
        cp16(bDst + so + SOFF_BH * 2,       bSrcH + (size_t)c * bStep);
        cp16(bDst + so + SOFF_BH * 2 + 16,  bSrcH + (size_t)c * bStep + 8);
        cp16(bDst + so + SOFF_BL * 2,       bSrcL + (size_t)c * bStep);
        cp16(bDst + so + SOFF_BL * 2 + 16,  bSrcL + (size_t)c * bStep + 8);
        cp_commit();
    };

    issue(0, 0);

    for (int i = 0; i < nch; i++) {
        if (i + 1 < nch) {
            issue(i + 1, (i + 1) & 1);
            cp_wait<1>();
        } else {
            cp_wait<0>();
        }
        __syncthreads();

        unsigned so = (unsigned)((i & 1) * STAGE_HW * 2);
        unsigned sAh = sBase + so;
        unsigned sAl = sBase + so + SOFF_AL * 2;
        unsigned sBh = sBase + so + SOFF_BH * 2;
        unsigned sBl = sBase + so + SOFF_BL * 2;

#pragma unroll
        for (int ks = 0; ks < 32; ks += 16) {
            unsigned Ahf[2][4], Alf[2][4];
#pragma unroll
            for (int ma = 0; ma < 2; ma++) {
                unsigned off = (unsigned)(((wm + (ma << 4) + lr + selR) * APAD
                                           + ks + selC) * 2);
                ldsm_x4(Ahf[ma][0], Ahf[ma][1], Ahf[ma][2], Ahf[ma][3], sAh + off);
                ldsm_x4(Alf[ma][0], Alf[ma][1], Alf[ma][2], Alf[ma][3], sAl + off);
            }
#pragma unroll
            for (int ng = 0; ng < 4; ng++) {
                unsigned boff = (unsigned)(((ks + lr + selR) * BPAD
                                            + wn + (ng << 4) + selC) * 2);
                unsigned Bh0, Bh1, Bh2, Bh3, Bl0, Bl1, Bl2, Bl3;
                ldsm_x4_t(Bh0, Bh1, Bh2, Bh3, sBh + boff);
                ldsm_x4_t(Bl0, Bl1, Bl2, Bl3, sBl + boff);
                float* c00 = Cacc[0][(ng << 1) + 0];
                float* c01 = Cacc[0][(ng << 1) + 1];
                float* c10 = Cacc[1][(ng << 1) + 0];
                float* c11 = Cacc[1][(ng << 1) + 1];
                // term-major order: same-accumulator reuse distance = 4
                mma_bf16(c00, Ahf[0][0], Ahf[0][1], Ahf[0][2], Ahf[0][3], Bh0, Bh1);
                mma_bf16(c01, Ahf[0][0], Ahf[0][1], Ahf[0][2], Ahf[0][3], Bh2, Bh3);
                mma_bf16(c10, Ahf[1][0], Ahf[1][1], Ahf[1][2], Ahf[1][3], Bh0, Bh1);
                mma_bf16(c11, Ahf[1][0], Ahf[1][1], Ahf[1][2], Ahf[1][3], Bh2, Bh3);
                mma_bf16(c00, Ahf[0][0], Ahf[0][1], Ahf[0][2], Ahf[0][3], Bl0, Bl1);
                mma_bf16(c01, Ahf[0][0], Ahf[0][1], Ahf[0][2], Ahf[0][3], Bl2, Bl3);
                mma_bf16(c10, Ahf[1][0], Ahf[1][1], Ahf[1][2], Ahf[1][3], Bl0, Bl1);
                mma_bf16(c11, Ahf[1][0], Ahf[1][1], Ahf[1][2], Ahf[1][3], Bl2, Bl3);
                mma_bf16(c00, Alf[0][0], Alf[0][1], Alf[0][2], Alf[0][3], Bh0, Bh1);
                mma_bf16(c01, Alf[0][0], Alf[0][1], Alf[0][2], Alf[0][3], Bh2, Bh3);
                mma_bf16(c10, Alf[1][0], Alf[1][1], Alf[1][2], Alf[1][3], Bh0, Bh1);
                mma_bf16(c11, Alf[1][0], Alf[1][1], Alf[1][2], Alf[1][3], Bh2, Bh3);
            }
        }
        __syncthreads();
    }

    // ---- epilogue: add bias (+Res) into Cacc ----
#pragma unroll
    for (int ma = 0; ma < 2; ma++) {
        int r0 = mBase + wm + (ma << 4) + (lane >> 2);
        int r1 = r0 + 8;
#pragma unroll
        for (int na = 0; na < 8; na++) {
            int c = nBase + wn + (na << 3) + ((lane & 3) << 1);
            float b0 = __ldg(bias + c), b1 = __ldg(bias + c + 1);
            float* cc = Cacc[ma][na];
            cc[0] += b0; cc[1] += b1; cc[2] += b0; cc[3] += b1;
            if (Res) {
                if (r0 < M) {
                    size_t o = (size_t)r0 * Nn + c;
                    cc[0] += Res[o]; cc[1] += Res[o + 1];
                }
                if (r1 < M) {
                    size_t o = (size_t)r1 * Nn + c;
                    cc[2] += Res[o]; cc[3] += Res[o + 1];
                }
            }
        }
    }

    if (!Yout) {
#pragma unroll
        for (int ma = 0; ma < 2; ma++) {
            int r0 = mBase + wm + (ma << 4) + (lane >> 2);
            int r1 = r0 + 8;
#pragma unroll
            for (int na = 0; na < 8; na++) {
                int c = nBase + wn + (na << 3) + ((lane & 3) << 1);
                const float* cc = Cacc[ma][na];
                if (r0 < M)
                    *(float2*)(Cc + (size_t)r0 * Nn + c) = make_float2(cc[0], cc[1]);
                if (r1 < M)
                    *(float2*)(Cc + (size_t)r1 * Nn + c) = make_float2(cc[2], cc[3]);
            }
        }
        return;
    }

    // ---- fused prenorm path (Nn == 128, single n-tile) ----
    float* red = (float*)smp;
    const int half = wid >> 2;
#pragma unroll
    for (int ma = 0; ma < 2; ma++) {
        int lr0 = wm + (ma << 4) + (lane >> 2);
        float s0 = 0.f, q0 = 0.f, s1 = 0.f, q1 = 0.f;
#pragma unroll
        for (int na = 0; na < 8; na++) {
            const float* cc = Cacc[ma][na];
            s0 += cc[0] + cc[1]; q0 += cc[0]*cc[0] + cc[1]*cc[1];
            s1 += cc[2] + cc[3]; q1 += cc[2]*cc[2] + cc[3]*cc[3];
        }
#pragma unroll
        for (int o = 1; o < 4; o <<= 1) {
            s0 += __shfl_xor_sync(0xffffffffu, s0, o);
            q0 += __shfl_xor_sync(0xffffffffu, q0, o);
            s1 += __shfl_xor_sync(0xffffffffu, s1, o);
            q1 += __shfl_xor_sync(0xffffffffu, q1, o);
        }
        if ((lane & 3) == 0) {
            red[(lr0 * 2 + half) * 2 + 0] = s0;
            red[(lr0 * 2 + half) * 2 + 1] = q0;
            red[((lr0 + 8) * 2 + half) * 2 + 0] = s1;
            red[((lr0 + 8) * 2 + half) * 2 + 1] = q1;
        }
    }
    __syncthreads();
#pragma unroll
    for (int ma = 0; ma < 2; ma++) {
        int lr0 = wm + (ma << 4) + (lane >> 2);
#pragma unroll
        for (int rr = 0; rr < 2; rr++) {
            int lrw = lr0 + rr * 8;
            int r = mBase + lrw;
            float s = red[(lrw * 2 + 0) * 2 + 0] + red[(lrw * 2 + 1) * 2 + 0];
            float q = red[(lrw * 2 + 0) * 2 + 1] + red[(lrw * 2 + 1) * 2 + 1];
            float mean = s * (1.f / 128.f);
            float var = q * (1.f / 128.f) - mean * mean;
            float rs = rsqrtf(var + 1e-5f);
            if (r < M) {
#pragma unroll
                for (int na = 0; na < 8; na++) {
                    int c = wn + (na << 3) + ((lane & 3) << 1);
                    const float* cc = Cacc[ma][na];
                    float v0 = cc[rr * 2], v1 = cc[rr * 2 + 1];
                    size_t o = (size_t)r * Nn + c;
                    *(float2*)(Cc + o) = make_float2(v0, v1);
                    float g0 = __ldg(png + c), g1 = __ldg(png + c + 1);
                    float bb0 = __ldg(pnb + c), bb1 = __ldg(pnb + c + 1);
                    float y0 = fmaxf((v0 - mean) * rs * g0 + bb0, 0.f);
                    float y1 = fmaxf((v1 - mean) * rs * g1 + bb1, 0.f);
                    *(float2*)(Yout + o) = make_float2(y0, y1);
                }
            }
        }
    }
}

// ---------------- softmax aggregation: persistent warps, work-stealing ----------------
__global__ void __launch_bounds__(256) k_aggregate(
    const float* __restrict__ xin,
    __nv_bfloat16* __restrict__ outh, __nv_bfloat16* __restrict__ outl,
    const float* __restrict__ We, const float* __restrict__ be,
    const float* __restrict__ tp, int layer)
{
    __shared__ float sW0[HH], sW1[HH], sB[HH];
    int tid = threadIdx.x;
    if (tid < HH) { sW0[tid] = We[tid]; sW1[tid] = We[HH + tid]; sB[tid] = be[tid]; }
    __syncthreads();
    int lane = tid & 31, f0 = lane << 2;
    float tval = __ldg(tp + layer);

    float w0x = sW0[f0], w0y = sW0[f0+1], w0z = sW0[f0+2], w0w = sW0[f0+3];
    float w1x = sW1[f0], w1y = sW1[f0+1], w1z = sW1[f0+2], w1w = sW1[f0+3];
    float bx  = sB[f0],  by  = sB[f0+1],  bz  = sB[f0+2],  bw  = sB[f0+3];

    for (;;) {
        unsigned base;
        if (lane == 0) base = atomicAdd(&g_wctr[layer], 4u);
        base = __shfl_sync(0xffffffffu, base, 0);
        if (base >= NN) break;
        int end = (int)base + 4;
        if (end > NN) end = NN;
        for (int gw = (int)base; gw < end; gw++) {
            int s0 = g_off[gw], s1 = g_off[gw + 1];
            float d0=0.f,d1=0.f,d2=0.f,d3=0.f,n0=0.f,n1=0.f,n2=0.f,n3=0.f;
            for (int j = s0; j < s1; j++) {
                int s = __ldg(&g_psrc[j]);
                float2 ea = __ldg(&g_pear[j]);
                float4 xv = __ldg((const float4*)(xin + (size_t)s * HH + f0));
                float p0 = fmaxf(xv.x + bx + ea.x*w0x + ea.y*w1x, 0.f) + 1e-7f;
                float p1 = fmaxf(xv.y + by + ea.x*w0y + ea.y*w1y, 0.f) + 1e-7f;
                float p2 = fmaxf(xv.z + bz + ea.x*w0z + ea.y*w1z, 0.f) + 1e-7f;
                float p3 = fmaxf(xv.w + bw + ea.x*w0w + ea.y*w1w, 0.f) + 1e-7f;
                float e0 = __expf(fminf(p0*tval, 80.f)); d0 += e0; n0 += p0*e0;
                float e1 = __expf(fminf(p1*tval, 80.f)); d1 += e1; n1 += p1*e1;
                float e2 = __expf(fminf(p2*tval, 80.f)); d2 += e2; n2 += p2*e2;
                float e3 = __expf(fminf(p3*tval, 80.f)); d3 += e3; n3 += p3*e3;
            }
            float4 xs = __ldg((const float4*)(xin + (size_t)gw * HH + f0));
            float o0 = n0 / (d0 + 1e-16f) + xs.x;
            float o1 = n1 / (d1 + 1e-16f) + xs.y;
            float o2 = n2 / (d2 + 1e-16f) + xs.z;
            float o3 = n3 / (d3 + 1e-16f) + xs.w;

            __nv_bfloat16 h0, l0, h1, l1, h2, l2, h3, l3;
            split2(o0, h0, l0); split2(o1, h1, l1);
            split2(o2, h2, l2); split2(o3, h3, l3);
            size_t ob = (size_t)gw * HH + f0;
            *(__nv_bfloat162*)(outh + ob)     = __halves2bfloat162(h0, h1);
            *(__nv_bfloat162*)(outh + ob + 2) = __halves2bfloat162(h2, h3);
            *(__nv_bfloat162*)(outl + ob)     = __halves2bfloat162(l0, l1);
            *(__nv_bfloat162*)(outl + ob + 2) = __halves2bfloat162(l2, l3);
        }
    }
}

// ---------------- LN+relu 256 -> bf16 hi/lo ----------------
__global__ void __launch_bounds__(256) k_lnrelu256(
    const float* __restrict__ x,
    __nv_bfloat16* __restrict__ outh, __nv_bfloat16* __restrict__ outl,
    const float* __restrict__ g, const float* __restrict__ b)
{
    int tid = threadIdx.x;
    int gw = (blockIdx.x << 3) + (tid >> 5);
    if (gw >= NN) return;
    int lane = tid & 31, f0 = lane << 3;
    const float* row = x + (size_t)gw * HB2;
    float4 a = *(const float4*)(row + f0);
    float4 c = *(const float4*)(row + f0 + 4);
    float s = a.x+a.y+a.z+a.w + c.x+c.y+c.z+c.w;
    float q = a.x*a.x+a.y*a.y+a.z*a.z+a.w*a.w + c.x*c.x+c.y*c.y+c.z*c.z+c.w*c.w;
    s = wred(s); q = wred(q);
    float mean = s * (1.f / HB2);
    float var = q * (1.f / HB2) - mean * mean;
    float rs = rsqrtf(var + 1e-5f);
    float4 g0 = *(const float4*)(g + f0), g1 = *(const float4*)(g + f0 + 4);
    float4 b0 = *(const float4*)(b + f0), b1 = *(const float4*)(b + f0 + 4);
    float v[8];
    v[0] = fmaxf((a.x - mean)*rs*g0.x + b0.x, 0.f);
    v[1] = fmaxf((a.y - mean)*rs*g0.y + b0.y, 0.f);
    v[2] = fmaxf((a.z - mean)*rs*g0.z + b0.z, 0.f);
    v[3] = fmaxf((a.w - mean)*rs*g0.w + b0.w, 0.f);
    v[4] = fmaxf((c.x - mean)*rs*g1.x + b1.x, 0.f);
    v[5] = fmaxf((c.y - mean)*rs*g1.y + b1.y, 0.f);
    v[6] = fmaxf((c.z - mean)*rs*g1.z + b1.z, 0.f);
    v[7] = fmaxf((c.w - mean)*rs*g1.w + b1.w, 0.f);
    size_t ob = (size_t)gw * HB2 + f0;
#pragma unroll
    for (int j = 0; j < 8; j += 2) {
        __nv_bfloat16 h0 = __float2bfloat16_rn(v[j]);
        __nv_bfloat16 h1 = __float2bfloat16_rn(v[j + 1]);
        *(__nv_bfloat162*)(outh + ob + j) = __halves2bfloat162(h0, h1);
        *(__nv_bfloat162*)(outl + ob + j) = __halves2bfloat162(
            __float2bfloat16_rn(v[j]     - __bfloat162float(h0)),
            __float2bfloat16_rn(v[j + 1] - __bfloat162float(h1)));
    }
}

// ---------------- final ----------------
__global__ void __launch_bounds__(256) k_final(
    const float* __restrict__ x, const float* __restrict__ g, const float* __restrict__ b,
    const float* __restrict__ Wo, const float* __restrict__ bo, float* __restrict__ out)
{
    __shared__ float sW[HH * CO];
    __shared__ float sbo[CO];
    int tid = threadIdx.x;
    for (int i = tid; i < HH * CO; i += 256) sW[i] = Wo[i];
    if (tid < CO) sbo[tid] = bo[tid];
    __syncthreads();
    int gw = (blockIdx.x << 3) + (tid >> 5);
    if (gw >= NN) return;
    int lane = tid & 31, f0 = lane << 2;
    float4 xv = *(const float4*)(x + (size_t)gw * HH + f0);
    float s = xv.x + xv.y + xv.z + xv.w;
    float q = xv.x*xv.x + xv.y*xv.y + xv.z*xv.z + xv.w*xv.w;
    s = wred(s); q = wred(q);
    float mean = s * (1.f / HH);
    float var = q * (1.f / HH) - mean * mean;
    float rs = rsqrtf(var + 1e-5f);
    float4 gv = *(const float4*)(g + f0), bv = *(const float4*)(b + f0);
    float f[4];
    f[0] = fmaxf((xv.x - mean)*rs*gv.x + bv.x, 0.f);
    f[1] = fmaxf((xv.y - mean)*rs*gv.y + bv.y, 0.f);
    f[2] = fmaxf((xv.z - mean)*rs*gv.z + bv.z, 0.f);
    f[3] = fmaxf((xv.w - mean)*rs*gv.w + bv.w, 0.f);
    float l0 = 0.f, l1 = 0.f, l2 = 0.f, l3 = 0.f;
#pragma unroll
    for (int k = 0; k < 4; k++) {
        const float* wr = sW + (f0 + k) * CO;
        l0 += f[k] * wr[0]; l1 += f[k] * wr[1];
        l2 += f[k] * wr[2]; l3 += f[k] * wr[3];
    }
    l0 = wred(l0); l1 = wred(l1); l2 = wred(l2); l3 = wred(l3);
    if (lane == 0) {
        l0 += sbo[0]; l1 += sbo[1]; l2 += sbo[2]; l3 += sbo[3];
        float m = fmaxf(fmaxf(l0, l1), fmaxf(l2, l3));
        float sum = expf(l0 - m) + expf(l1 - m) + expf(l2 - m) + expf(l3 - m);
        float lse = m + logf(sum);
        float* o = out + (size_t)gw * CO;
        o[0] = l0 - lse; o[1] = l1 - lse; o[2] = l2 - lse; o[3] = l3 - lse;
    }
}

// ---------------- launch ----------------
extern "C" void kernel_launch(void* const* d_in, const int* in_sizes, int n_in,
                              void* d_out, int out_size)
{
    (void)in_sizes; (void)n_in; (void)out_size;
    const float* node_x = (const float*)d_in[0];
    const float* ear    = (const float*)d_in[1];
    const int*   eidx   = (const int*)  d_in[2];
    const float* Wn     = (const float*)d_in[3];
    const float* bn     = (const float*)d_in[4];
    const float* We     = (const float*)d_in[5];
    const float* be     = (const float*)d_in[6];
    const float* tt     = (const float*)d_in[7];
    const float* W1     = (const float*)d_in[8];
    const float* b1     = (const float*)d_in[9];
    const float* lng    = (const float*)d_in[10];
    const float* lnb    = (const float*)d_in[11];
    const float* W2     = (const float*)d_in[12];
    const float* b2     = (const float*)d_in[13];
    const float* dng    = (const float*)d_in[14];
    const float* dnb    = (const float*)d_in[15];
    const float* Wout   = (const float*)d_in[16];
    const float* bout   = (const float*)d_in[17];
    float* out = (float*)d_out;
    const int* src = eidx;
    const int* dst = eidx + NE;

    float *px0, *px, *py, *pmid;
    __nv_bfloat16 *paggh, *paggl, *pmidh, *pmidl, *pwh, *pwl, *pwnh, *pwnl, *pxh, *pxl;
    cudaGetSymbolAddress((void**)&px0,   g_x0);
    cudaGetSymbolAddress((void**)&px,    g_x);
    cudaGetSymbolAddress((void**)&py,    g_y);
    cudaGetSymbolAddress((void**)&pmid,  g_mid);
    cudaGetSymbolAddress((void**)&paggh, g_aggh);
    cudaGetSymbolAddress((void**)&paggl, g_aggl);
    cudaGetSymbolAddress((void**)&pmidh, g_midh);
    cudaGetSymbolAddress((void**)&pmidl, g_midl);
    cudaGetSymbolAddress((void**)&pwh,   g_bwh);
    cudaGetSymbolAddress((void**)&pwl,   g_bwl);
    cudaGetSymbolAddress((void**)&pwnh,  g_wnh);
    cudaGetSymbolAddress((void**)&pwnl,  g_wnl);
    cudaGetSymbolAddress((void**)&pxh,   g_xh);
    cudaGetSymbolAddress((void**)&pxl,   g_xl);

    cudaFuncSetAttribute(k_gemm_pipe,
                         cudaFuncAttributeMaxDynamicSharedMemorySize,
                         SMEM_PIPE_BYTES);

    const int MB = (NN + 127) / 128;

    // 1: prep
    k_prep<<<(PREP_Z4 + 255) / 256, 256>>>(Wn, W1, W2, node_x);
    // 2-3: CSR histogram + block scan
    k_hist<<<(NE + 255) / 256, 256>>>(dst);
    k_scan1<<<49, 1024>>>();
    // 4: encoder GEMM (ncu capture window)
    k_gemm_pipe<<<dim3(1, MB), 256, SMEM_PIPE_BYTES>>>(
        pxh, pxl, pwnh, pwnl, bn, nullptr, px0, NN, KPAD, HH,
        nullptr, nullptr, nullptr);
    // 5-7: finish CSR
    k_scan2<<<1, 64>>>();
    k_scan3<<<49, 1024>>>();
    k_scatter<<<(NE + 255) / 256, 256>>>(src, dst, (const float2*)ear);

    const float* xin = px0;
    for (int l = 0; l < 3; l++) {
        k_aggregate<<<592, 256>>>(xin, paggh, paggl, We, be, tt, l);
        k_gemm_pipe<<<dim3(2, MB), 256, SMEM_PIPE_BYTES>>>(
            paggh, paggl,
            pwh + OFF_W1 + l * SZ_W1, pwl + OFF_W1 + l * SZ_W1,
            b1 + l * HB2, nullptr, pmid, NN, HH, HB2,
            nullptr, nullptr, nullptr);
        k_lnrelu256<<<6250, 256>>>(pmid, pmidh, pmidl, lng + l * HB2, lnb + l * HB2);
        const float* png = (l < 2) ? (dng + (l + 1) * HH) : nullptr;
        const float* pnb = (l < 2) ? (dnb + (l + 1) * HH) : nullptr;
        float* yout = (l < 2) ? py : nullptr;
        k_gemm_pipe<<<dim3(1, MB), 256, SMEM_PIPE_BYTES>>>(
            pmidh, pmidl,
            pwh + OFF_W2 + l * SZ_W2, pwl + OFF_W2 + l * SZ_W2,
            b2 + l * HH, (l == 0) ? nullptr : px, px, NN, HB2, HH,
            png, pnb, yout);
        xin = py;
    }
    k_final<<<6250, 256>>>(px, dng, dnb, Wout, bout, out);
}

// round 14
// speedup vs baseline: 1.1219x; 1.1219x over previous
#include <cuda_runtime.h>
#include <cuda_bf16.h>
#include <stdint.h>
#include <float.h>
#include <math.h>

#define NN 50000
#define NE 400000
#define FIN 514
#define KPAD 544
#define HH 128
#define HB2 256
#define CO 4

#define SZ_W1  (HH*HB2)
#define SZ_W2  (HB2*HH)
#define OFF_W1 0
#define OFF_W2 (3*SZ_W1)
#define WTOT   (OFF_W2 + 3*SZ_W2)

// ---------------- scratch ----------------
__device__ __align__(256) float g_x0 [NN*HH];
__device__ __align__(256) float g_x  [NN*HH];
__device__ __align__(256) float g_y  [NN*HH];
__device__ __align__(256) float g_mid[NN*HB2];
__device__ __align__(256) __nv_bfloat16 g_aggh[NN*HH];
__device__ __align__(256) __nv_bfloat16 g_aggl[NN*HH];
__device__ __align__(256) __nv_bfloat16 g_midh[NN*HB2];
__device__ __align__(256) __nv_bfloat16 g_midl[NN*HB2];
__device__ __align__(256) __nv_bfloat16 g_bwh[WTOT];
__device__ __align__(256) __nv_bfloat16 g_bwl[WTOT];
__device__ __align__(256) __nv_bfloat16 g_wnh[KPAD*HH];
__device__ __align__(256) __nv_bfloat16 g_wnl[KPAD*HH];
__device__ __align__(256) __nv_bfloat16 g_xh[(size_t)NN*KPAD];
__device__ __align__(256) __nv_bfloat16 g_xl[(size_t)NN*KPAD];
__device__ int g_cnt[NN];
__device__ int g_off[NN+1];
__device__ int g_bsum[64];
__device__ unsigned g_wctr[4];
__device__ int g_psrc[NE];
__device__ __align__(256) float2 g_pear[NE];

// ---------------- helpers ----------------
__device__ __forceinline__ float wred(float v) {
#pragma unroll
    for (int o = 16; o > 0; o >>= 1) v += __shfl_xor_sync(0xffffffffu, v, o);
    return v;
}

__device__ __forceinline__ void mma_bf16(float c[4],
    unsigned a0, unsigned a1, unsigned a2, unsigned a3,
    unsigned b0, unsigned b1)
{
    asm volatile(
        "mma.sync.aligned.m16n8k16.row.col.f32.bf16.bf16.f32 "
        "{%0,%1,%2,%3}, {%4,%5,%6,%7}, {%8,%9}, {%0,%1,%2,%3};\n"
        : "+f"(c[0]), "+f"(c[1]), "+f"(c[2]), "+f"(c[3])
        : "r"(a0), "r"(a1), "r"(a2), "r"(a3), "r"(b0), "r"(b1));
}

__device__ __forceinline__ void ldsm_x4(unsigned& r0, unsigned& r1,
                                        unsigned& r2, unsigned& r3, unsigned addr)
{
    asm volatile("ldmatrix.sync.aligned.m8n8.x4.shared.b16 {%0,%1,%2,%3}, [%4];\n"
        : "=r"(r0), "=r"(r1), "=r"(r2), "=r"(r3) : "r"(addr));
}

__device__ __forceinline__ void ldsm_x4_t(unsigned& r0, unsigned& r1,
                                          unsigned& r2, unsigned& r3, unsigned addr)
{
    asm volatile("ldmatrix.sync.aligned.m8n8.x4.trans.shared.b16 {%0,%1,%2,%3}, [%4];\n"
        : "=r"(r0), "=r"(r1), "=r"(r2), "=r"(r3) : "r"(addr));
}

__device__ __forceinline__ void cp16(unsigned dst, const void* src) {
    asm volatile("cp.async.cg.shared.global [%0], [%1], 16;\n" :: "r"(dst), "l"(src));
}
__device__ __forceinline__ void cp_commit() {
    asm volatile("cp.async.commit_group;\n");
}
template<int Ngrp> __device__ __forceinline__ void cp_wait() {
    asm volatile("cp.async.wait_group %0;\n" :: "n"(Ngrp));
}

__device__ __forceinline__ void split2(float v, __nv_bfloat16& h, __nv_bfloat16& l) {
    h = __float2bfloat16_rn(v);
    l = __float2bfloat16_rn(v - __bfloat162float(h));
}

// ---------------- prep ----------------
#define PREP_Z0 (NN)
#define PREP_Z1 (PREP_Z0 + KPAD*HH)
#define PREP_Z2 (PREP_Z1 + 3*SZ_W1)
#define PREP_Z3 (PREP_Z2 + 3*SZ_W2)
#define XF2     (KPAD/2)
#define PREP_Z4 (PREP_Z3 + NN*XF2)

__global__ void k_prep(const float* __restrict__ Wn, const float* __restrict__ W1,
                       const float* __restrict__ W2, const float* __restrict__ X)
{
    int idx = blockIdx.x * blockDim.x + threadIdx.x;
    if (idx < PREP_Z0) { g_cnt[idx] = 0; return; }
    if (idx < PREP_Z1) {
        int j = idx - PREP_Z0;
        int r = j >> 7;
        int c = j & 127;
        float v = (r < FIN) ? Wn[r * HH + c] : 0.f;
        __nv_bfloat16 h, l; split2(v, h, l);
        g_wnh[j] = h; g_wnl[j] = l;
        return;
    }
    if (idx < PREP_Z2) {
        int j = idx - PREP_Z1;
        __nv_bfloat16 h, l; split2(W1[j], h, l);
        g_bwh[OFF_W1 + j] = h; g_bwl[OFF_W1 + j] = l;
        return;
    }
    if (idx < PREP_Z3) {
        int j = idx - PREP_Z2;
        __nv_bfloat16 h, l; split2(W2[j], h, l);
        g_bwh[OFF_W2 + j] = h; g_bwl[OFF_W2 + j] = l;
        return;
    }
    if (idx < PREP_Z4) {
        int j = idx - PREP_Z3;
        int row = j / XF2;
        int c2 = j - row * XF2;
        float2 v;
        if (c2 * 2 < FIN) v = *(const float2*)(X + (size_t)row * FIN + c2 * 2);
        else              v = make_float2(0.f, 0.f);
        __nv_bfloat16 h0, l0, h1, l1;
        split2(v.x, h0, l0); split2(v.y, h1, l1);
        size_t o = (size_t)row * KPAD + c2 * 2;
        *(__nv_bfloat162*)(g_xh + o) = __halves2bfloat162(h0, h1);
        *(__nv_bfloat162*)(g_xl + o) = __halves2bfloat162(l0, l1);
    }
}

// ---------------- CSR build ----------------
__global__ void k_hist(const int* __restrict__ dst) {
    int e = blockIdx.x * blockDim.x + threadIdx.x;
    if (e < NE) atomicAdd(&g_cnt[dst[e]], 1);
}

__global__ void __launch_bounds__(1024) k_scan1() {
    __shared__ int wsum[32];
    int tid = threadIdx.x;
    int i = blockIdx.x * 1024 + tid;
    int v = (i < NN) ? g_cnt[i] : 0;
    int x = v;
    int lane = tid & 31;
#pragma unroll
    for (int o = 1; o < 32; o <<= 1) {
        int t = __shfl_up_sync(0xffffffffu, x, o);
        if (lane >= o) x += t;
    }
    if (lane == 31) wsum[tid >> 5] = x;
    __syncthreads();
    if (tid < 32) {
        int orig = wsum[tid];
        int y = orig;
#pragma unroll
        for (int o = 1; o < 32; o <<= 1) {
            int t = __shfl_up_sync(0xffffffffu, y, o);
            if (tid >= o) y += t;
        }
        wsum[tid] = y - orig;
    }
    __syncthreads();
    int excl = x - v + wsum[tid >> 5];
    if (i < NN) g_off[i] = excl;
    if (tid == 1023) g_bsum[blockIdx.x] = excl + v;
}

__global__ void k_scan2() {
    __shared__ int s[64];
    int tid = threadIdx.x;
    if (tid < 4) g_wctr[tid] = 0u;
    int v = (tid < 49) ? g_bsum[tid] : 0;
    s[tid] = v;
    __syncthreads();
    for (int o = 1; o < 64; o <<= 1) {
        int t = (tid >= o) ? s[tid - o] : 0;
        __syncthreads();
        s[tid] += t;
        __syncthreads();
    }
    if (tid < 49) g_bsum[tid] = s[tid] - v;
    if (tid == 48) g_off[NN] = s[48];
}

__global__ void __launch_bounds__(1024) k_scan3() {
    int i = blockIdx.x * 1024 + threadIdx.x;
    if (i < NN) {
        int t = g_off[i] + g_bsum[blockIdx.x];
        g_off[i] = t;
        g_cnt[i] = t;
    }
}

__global__ void k_scatter(const int* __restrict__ src, const int* __restrict__ dst,
                          const float2* __restrict__ ear) {
    int e = blockIdx.x * blockDim.x + threadIdx.x;
    if (e >= NE) return;
    int d = dst[e];
    int pos = atomicAdd(&g_cnt[d], 1);
    g_psrc[pos] = src[e];
    g_pear[pos] = ear[e];
}

// ---------------- GEMM layout ----------------
#define APAD 40
#define BPAD 136
#define SOFF_AL (128*APAD)
#define SOFF_BH (2*128*APAD)
#define SOFF_BL (SOFF_BH + 32*BPAD)
#define STAGE_HW (SOFF_BL + 32*BPAD)
#define SMEM_PIPE_BYTES (2 * STAGE_HW * 2)

// ---------------- pipelined GEMM, tile 128x128, 256 threads (R12 proven order) ----------------
__global__ void __launch_bounds__(256, 2) k_gemm_pipe(
    const __nv_bfloat16* __restrict__ Ah, const __nv_bfloat16* __restrict__ Al,
    const __nv_bfloat16* __restrict__ Bh, const __nv_bfloat16* __restrict__ Bl,
    const float* __restrict__ bias, const float* __restrict__ Res,
    float* __restrict__ Cc, int M, int K, int Nn,
    const float* __restrict__ png, const float* __restrict__ pnb,
    float* __restrict__ Yout)
{
    extern __shared__ __nv_bfloat16 smp[];
    const int tid = threadIdx.x;
    const int lane = tid & 31;
    const int wid = tid >> 5;
    const int wm = (wid & 3) << 5;
    const int wn = (wid >> 2) << 6;
    const int mBase = blockIdx.y << 7;
    const int nBase = blockIdx.x << 7;

    const int lr = lane & 7;
    const int sel = lane >> 3;
    const int selR = (sel & 1) << 3;
    const int selC = (sel >> 1) << 3;

    const unsigned sBase = (unsigned)__cvta_generic_to_shared(&smp[0]);

    const int arow = tid >> 1;
    const int acol = (tid & 1) << 4;
    const int brow = tid >> 3;
    const int bcol = (tid & 7) << 4;

    const int gmRaw = mBase + arow;
    const int gmCl = (gmRaw < M) ? gmRaw : (M - 1);
    const __nv_bfloat16* aSrcH = Ah + (size_t)gmCl * K + acol;
    const __nv_bfloat16* aSrcL = Al + (size_t)gmCl * K + acol;
    const __nv_bfloat16* bSrcH = Bh + (size_t)brow * Nn + nBase + bcol;
    const __nv_bfloat16* bSrcL = Bl + (size_t)brow * Nn + nBase + bcol;
    const size_t bStep = (size_t)32 * Nn;

    const unsigned aDst = sBase + (unsigned)((arow * APAD + acol) * 2);
    const unsigned bDst = sBase + (unsigned)((brow * BPAD + bcol) * 2);

    float Cacc[2][8][4];
#pragma unroll
    for (int i = 0; i < 2; i++)
#pragma unroll
        for (int j = 0; j < 8; j++)
#pragma unroll
            for (int q = 0; q < 4; q++) Cacc[i][j][q] = 0.f;

    const int nch = K >> 5;

    auto issue = [&](int c, int s) {
        unsigned so = (unsigned)(s * STAGE_HW * 2);
        int k0 = c << 5;
        cp16(aDst + so,                     aSrcH + (size_t)k0);
        cp16(aDst + so + 16,                aSrcH + (size_t)k0 + 8);
        cp16(aDst + so + SOFF_AL * 2,       aSrcL + (size_t)k0);
        cp16(aDst + so + SOFF_AL * 2 + 16,  aSrcL + (size_t)k0 + 8);
        cp16(bDst + so + SOFF_BH * 2,       bSrcH + (size_t)c * bStep);
        cp16(bDst + so + SOFF_BH * 2 + 16,  bSrcH + (size_t)c * bStep + 8);
        cp16(bDst + so + SOFF_BL * 2,       bSrcL + (size_t)c * bStep);
        cp16(bDst + so + SOFF_BL * 2 + 16,  bSrcL + (size_t)c * bStep + 8);
        cp_commit();
    };

    issue(0, 0);

    for (int i = 0; i < nch; i++) {
        if (i + 1 < nch) {
            issue(i + 1, (i + 1) & 1);
            cp_wait<1>();
        } else {
            cp_wait<0>();
        }
        __syncthreads();

        unsigned so = (unsigned)((i & 1) * STAGE_HW * 2);
        unsigned sAh = sBase + so;
        unsigned sAl = sBase + so + SOFF_AL * 2;
        unsigned sBh = sBase + so + SOFF_BH * 2;
        unsigned sBl = sBase + so + SOFF_BL * 2;

#pragma unroll
        for (int ks = 0; ks < 32; ks += 16) {
            unsigned Ahf[2][4], Alf[2][4];
#pragma unroll
            for (int ma = 0; ma < 2; ma++) {
                unsigned off = (unsigned)(((wm + (ma << 4) + lr + selR) * APAD
                                           + ks + selC) * 2);
                ldsm_x4(Ahf[ma][0], Ahf[ma][1], Ahf[ma][2], Ahf[ma][3], sAh + off);
                ldsm_x4(Alf[ma][0], Alf[ma][1], Alf[ma][2], Alf[ma][3], sAl + off);
            }
#pragma unroll
            for (int ng = 0; ng < 4; ng++) {
                unsigned boff = (unsigned)(((ks + lr + selR) * BPAD
                                            + wn + (ng << 4) + selC) * 2);
                unsigned Bh0, Bh1, Bh2, Bh3, Bl0, Bl1, Bl2, Bl3;
                ldsm_x4_t(Bh0, Bh1, Bh2, Bh3, sBh + boff);
                ldsm_x4_t(Bl0, Bl1, Bl2, Bl3, sBl + boff);
#pragma unroll
                for (int ma = 0; ma < 2; ma++) {
                    float* c0 = Cacc[ma][(ng << 1) + 0];
                    float* c1 = Cacc[ma][(ng << 1) + 1];
                    mma_bf16(c0, Ahf[ma][0], Ahf[ma][1], Ahf[ma][2], Ahf[ma][3], Bh0, Bh1);
                    mma_bf16(c0, Ahf[ma][0], Ahf[ma][1], Ahf[ma][2], Ahf[ma][3], Bl0, Bl1);
                    mma_bf16(c0, Alf[ma][0], Alf[ma][1], Alf[ma][2], Alf[ma][3], Bh0, Bh1);
                    mma_bf16(c1, Ahf[ma][0], Ahf[ma][1], Ahf[ma][2], Ahf[ma][3], Bh2, Bh3);
                    mma_bf16(c1, Ahf[ma][0], Ahf[ma][1], Ahf[ma][2], Ahf[ma][3], Bl2, Bl3);
                    mma_bf16(c1, Alf[ma][0], Alf[ma][1], Alf[ma][2], Alf[ma][3], Bh2, Bh3);
                }
            }
        }
        __syncthreads();
    }

    // ---- epilogue: add bias (+Res) into Cacc ----
#pragma unroll
    for (int ma = 0; ma < 2; ma++) {
        int r0 = mBase + wm + (ma << 4) + (lane >> 2);
        int r1 = r0 + 8;
#pragma unroll
        for (int na = 0; na < 8; na++) {
            int c = nBase + wn + (na << 3) + ((lane & 3) << 1);
            float b0 = __ldg(bias + c), b1 = __ldg(bias + c + 1);
            float* cc = Cacc[ma][na];
            cc[0] += b0; cc[1] += b1; cc[2] += b0; cc[3] += b1;
            if (Res) {
                if (r0 < M) {
                    size_t o = (size_t)r0 * Nn + c;
                    cc[0] += Res[o]; cc[1] += Res[o + 1];
                }
                if (r1 < M) {
                    size_t o = (size_t)r1 * Nn + c;
                    cc[2] += Res[o]; cc[3] += Res[o + 1];
                }
            }
        }
    }

    if (!Yout) {
#pragma unroll
        for (int ma = 0; ma < 2; ma++) {
            int r0 = mBase + wm + (ma << 4) + (lane >> 2);
            int r1 = r0 + 8;
#pragma unroll
            for (int na = 0; na < 8; na++) {
                int c = nBase + wn + (na << 3) + ((lane & 3) << 1);
                const float* cc = Cacc[ma][na];
                if (r0 < M)
                    *(float2*)(Cc + (size_t)r0 * Nn + c) = make_float2(cc[0], cc[1]);
                if (r1 < M)
                    *(float2*)(Cc + (size_t)r1 * Nn + c) = make_float2(cc[2], cc[3]);
            }
        }
        return;
    }

    // ---- fused prenorm path (Nn == 128, single n-tile) ----
    float* red = (float*)smp;
    const int half = wid >> 2;
#pragma unroll
    for (int ma = 0; ma < 2; ma++) {
        int lr0 = wm + (ma << 4) + (lane >> 2);
        float s0 = 0.f, q0 = 0.f, s1 = 0.f, q1 = 0.f;
#pragma unroll
        for (int na = 0; na < 8; na++) {
            const float* cc = Cacc[ma][na];
            s0 += cc[0] + cc[1]; q0 += cc[0]*cc[0] + cc[1]*cc[1];
            s1 += cc[2] + cc[3]; q1 += cc[2]*cc[2] + cc[3]*cc[3];
        }
#pragma unroll
        for (int o = 1; o < 4; o <<= 1) {
            s0 += __shfl_xor_sync(0xffffffffu, s0, o);
            q0 += __shfl_xor_sync(0xffffffffu, q0, o);
            s1 += __shfl_xor_sync(0xffffffffu, s1, o);
            q1 += __shfl_xor_sync(0xffffffffu, q1, o);
        }
        if ((lane & 3) == 0) {
            red[(lr0 * 2 + half) * 2 + 0] = s0;
            red[(lr0 * 2 + half) * 2 + 1] = q0;
            red[((lr0 + 8) * 2 + half) * 2 + 0] = s1;
            red[((lr0 + 8) * 2 + half) * 2 + 1] = q1;
        }
    }
    __syncthreads();
#pragma unroll
    for (int ma = 0; ma < 2; ma++) {
        int lr0 = wm + (ma << 4) + (lane >> 2);
#pragma unroll
        for (int rr = 0; rr < 2; rr++) {
            int lrw = lr0 + rr * 8;
            int r = mBase + lrw;
            float s = red[(lrw * 2 + 0) * 2 + 0] + red[(lrw * 2 + 1) * 2 + 0];
            float q = red[(lrw * 2 + 0) * 2 + 1] + red[(lrw * 2 + 1) * 2 + 1];
            float mean = s * (1.f / 128.f);
            float var = q * (1.f / 128.f) - mean * mean;
            float rs = rsqrtf(var + 1e-5f);
            if (r < M) {
#pragma unroll
                for (int na = 0; na < 8; na++) {
                    int c = wn + (na << 3) + ((lane & 3) << 1);
                    const float* cc = Cacc[ma][na];
                    float v0 = cc[rr * 2], v1 = cc[rr * 2 + 1];
                    size_t o = (size_t)r * Nn + c;
                    *(float2*)(Cc + o) = make_float2(v0, v1);
                    float g0 = __ldg(png + c), g1 = __ldg(png + c + 1);
                    float bb0 = __ldg(pnb + c), bb1 = __ldg(pnb + c + 1);
                    float y0 = fmaxf((v0 - mean) * rs * g0 + bb0, 0.f);
                    float y1 = fmaxf((v1 - mean) * rs * g1 + bb1, 0.f);
                    *(float2*)(Yout + o) = make_float2(y0, y1);
                }
            }
        }
    }
}

// ---------------- softmax aggregation: persistent warps, work-stealing ----------------
__global__ void __launch_bounds__(256) k_aggregate(
    const float* __restrict__ xin,
    __nv_bfloat16* __restrict__ outh, __nv_bfloat16* __restrict__ outl,
    const float* __restrict__ We, const float* __restrict__ be,
    const float* __restrict__ tp, int layer)
{
    __shared__ float sW0[HH], sW1[HH], sB[HH];
    int tid = threadIdx.x;
    if (tid < HH) { sW0[tid] = We[tid]; sW1[tid] = We[HH + tid]; sB[tid] = be[tid]; }
    __syncthreads();
    int lane = tid & 31, f0 = lane << 2;
    float tval = __ldg(tp + layer);

    float w0x = sW0[f0], w0y = sW0[f0+1], w0z = sW0[f0+2], w0w = sW0[f0+3];
    float w1x = sW1[f0], w1y = sW1[f0+1], w1z = sW1[f0+2], w1w = sW1[f0+3];
    float bx  = sB[f0],  by  = sB[f0+1],  bz  = sB[f0+2],  bw  = sB[f0+3];

    for (;;) {
        unsigned base;
        if (lane == 0) base = atomicAdd(&g_wctr[layer], 4u);
        base = __shfl_sync(0xffffffffu, base, 0);
        if (base >= NN) break;
        int end = (int)base + 4;
        if (end > NN) end = NN;
        for (int gw = (int)base; gw < end; gw++) {
            int s0 = g_off[gw], s1 = g_off[gw + 1];
            float d0=0.f,d1=0.f,d2=0.f,d3=0.f,n0=0.f,n1=0.f,n2=0.f,n3=0.f;
            for (int j = s0; j < s1; j++) {
                int s = __ldg(&g_psrc[j]);
                float2 ea = __ldg(&g_pear[j]);
                float4 xv = __ldg((const float4*)(xin + (size_t)s * HH + f0));
                float p0 = fmaxf(xv.x + bx + ea.x*w0x + ea.y*w1x, 0.f) + 1e-7f;
                float p1 = fmaxf(xv.y + by + ea.x*w0y + ea.y*w1y, 0.f) + 1e-7f;
                float p2 = fmaxf(xv.z + bz + ea.x*w0z + ea.y*w1z, 0.f) + 1e-7f;
                float p3 = fmaxf(xv.w + bw + ea.x*w0w + ea.y*w1w, 0.f) + 1e-7f;
                float e0 = __expf(fminf(p0*tval, 80.f)); d0 += e0; n0 += p0*e0;
                float e1 = __expf(fminf(p1*tval, 80.f)); d1 += e1; n1 += p1*e1;
                float e2 = __expf(fminf(p2*tval, 80.f)); d2 += e2; n2 += p2*e2;
                float e3 = __expf(fminf(p3*tval, 80.f)); d3 += e3; n3 += p3*e3;
            }
            float4 xs = __ldg((const float4*)(xin + (size_t)gw * HH + f0));
            float o0 = n0 / (d0 + 1e-16f) + xs.x;
            float o1 = n1 / (d1 + 1e-16f) + xs.y;
            float o2 = n2 / (d2 + 1e-16f) + xs.z;
            float o3 = n3 / (d3 + 1e-16f) + xs.w;

            __nv_bfloat16 h0, l0, h1, l1, h2, l2, h3, l3;
            split2(o0, h0, l0); split2(o1, h1, l1);
            split2(o2, h2, l2); split2(o3, h3, l3);
            size_t ob = (size_t)gw * HH + f0;
            *(__nv_bfloat162*)(outh + ob)     = __halves2bfloat162(h0, h1);
            *(__nv_bfloat162*)(outh + ob + 2) = __halves2bfloat162(h2, h3);
            *(__nv_bfloat162*)(outl + ob)     = __halves2bfloat162(l0, l1);
            *(__nv_bfloat162*)(outl + ob + 2) = __halves2bfloat162(l2, l3);
        }
    }
}

// ---------------- LN+relu 256 -> bf16 hi/lo ----------------
__global__ void __launch_bounds__(256) k_lnrelu256(
    const float* __restrict__ x,
    __nv_bfloat16* __restrict__ outh, __nv_bfloat16* __restrict__ outl,
    const float* __restrict__ g, const float* __restrict__ b)
{
    int tid = threadIdx.x;
    int gw = (blockIdx.x << 3) + (tid >> 5);
    if (gw >= NN) return;
    int lane = tid & 31, f0 = lane << 3;
    const float* row = x + (size_t)gw * HB2;
    float4 a = *(const float4*)(row + f0);
    float4 c = *(const float4*)(row + f0 + 4);
    float s = a.x+a.y+a.z+a.w + c.x+c.y+c.z+c.w;
    float q = a.x*a.x+a.y*a.y+a.z*a.z+a.w*a.w + c.x*c.x+c.y*c.y+c.z*c.z+c.w*c.w;
    s = wred(s); q = wred(q);
    float mean = s * (1.f / HB2);
    float var = q * (1.f / HB2) - mean * mean;
    float rs = rsqrtf(var + 1e-5f);
    float4 g0 = *(const float4*)(g + f0), g1 = *(const float4*)(g + f0 + 4);
    float4 b0 = *(const float4*)(b + f0), b1 = *(const float4*)(b + f0 + 4);
    float v[8];
    v[0] = fmaxf((a.x - mean)*rs*g0.x + b0.x, 0.f);
    v[1] = fmaxf((a.y - mean)*rs*g0.y + b0.y, 0.f);
    v[2] = fmaxf((a.z - mean)*rs*g0.z + b0.z, 0.f);
    v[3] = fmaxf((a.w - mean)*rs*g0.w + b0.w, 0.f);
    v[4] = fmaxf((c.x - mean)*rs*g1.x + b1.x, 0.f);
    v[5] = fmaxf((c.y - mean)*rs*g1.y + b1.y, 0.f);
    v[6] = fmaxf((c.z - mean)*rs*g1.z + b1.z, 0.f);
    v[7] = fmaxf((c.w - mean)*rs*g1.w + b1.w, 0.f);
    size_t ob = (size_t)gw * HB2 + f0;
#pragma unroll
    for (int j = 0; j < 8; j += 2) {
        __nv_bfloat16 h0 = __float2bfloat16_rn(v[j]);
        __nv_bfloat16 h1 = __float2bfloat16_rn(v[j + 1]);
        *(__nv_bfloat162*)(outh + ob + j) = __halves2bfloat162(h0, h1);
        *(__nv_bfloat162*)(outl + ob + j) = __halves2bfloat162(
            __float2bfloat16_rn(v[j]     - __bfloat162float(h0)),
            __float2bfloat16_rn(v[j + 1] - __bfloat162float(h1)));
    }
}

// ---------------- final ----------------
__global__ void __launch_bounds__(256) k_final(
    const float* __restrict__ x, const float* __restrict__ g, const float* __restrict__ b,
    const float* __restrict__ Wo, const float* __restrict__ bo, float* __restrict__ out)
{
    __shared__ float sW[HH * CO];
    __shared__ float sbo[CO];
    int tid = threadIdx.x;
    for (int i = tid; i < HH * CO; i += 256) sW[i] = Wo[i];
    if (tid < CO) sbo[tid] = bo[tid];
    __syncthreads();
    int gw = (blockIdx.x << 3) + (tid >> 5);
    if (gw >= NN) return;
    int lane = tid & 31, f0 = lane << 2;
    float4 xv = *(const float4*)(x + (size_t)gw * HH + f0);
    float s = xv.x + xv.y + xv.z + xv.w;
    float q = xv.x*xv.x + xv.y*xv.y + xv.z*xv.z + xv.w*xv.w;
    s = wred(s); q = wred(q);
    float mean = s * (1.f / HH);
    float var = q * (1.f / HH) - mean * mean;
    float rs = rsqrtf(var + 1e-5f);
    float4 gv = *(const float4*)(g + f0), bv = *(const float4*)(b + f0);
    float f[4];
    f[0] = fmaxf((xv.x - mean)*rs*gv.x + bv.x, 0.f);
    f[1] = fmaxf((xv.y - mean)*rs*gv.y + bv.y, 0.f);
    f[2] = fmaxf((xv.z - mean)*rs*gv.z + bv.z, 0.f);
    f[3] = fmaxf((xv.w - mean)*rs*gv.w + bv.w, 0.f);
    float l0 = 0.f, l1 = 0.f, l2 = 0.f, l3 = 0.f;
#pragma unroll
    for (int k = 0; k < 4; k++) {
        const float* wr = sW + (f0 + k) * CO;
        l0 += f[k] * wr[0]; l1 += f[k] * wr[1];
        l2 += f[k] * wr[2]; l3 += f[k] * wr[3];
    }
    l0 = wred(l0); l1 = wred(l1); l2 = wred(l2); l3 = wred(l3);
    if (lane == 0) {
        l0 += sbo[0]; l1 += sbo[1]; l2 += sbo[2]; l3 += sbo[3];
        float m = fmaxf(fmaxf(l0, l1), fmaxf(l2, l3));
        float sum = expf(l0 - m) + expf(l1 - m) + expf(l2 - m) + expf(l3 - m);
        float lse = m + logf(sum);
        float* o = out + (size_t)gw * CO;
        o[0] = l0 - lse; o[1] = l1 - lse; o[2] = l2 - lse; o[3] = l3 - lse;
    }
}

// ---------------- launch ----------------
extern "C" void kernel_launch(void* const* d_in, const int* in_sizes, int n_in,
                              void* d_out, int out_size)
{
    (void)in_sizes; (void)n_in; (void)out_size;
    const float* node_x = (const float*)d_in[0];
    const float* ear    = (const float*)d_in[1];
    const int*   eidx   = (const int*)  d_in[2];
    const float* Wn     = (const float*)d_in[3];
    const float* bn     = (const float*)d_in[4];
    const float* We     = (const float*)d_in[5];
    const float* be     = (const float*)d_in[6];
    const float* tt     = (const float*)d_in[7];
    const float* W1     = (const float*)d_in[8];
    const float* b1     = (const float*)d_in[9];
    const float* lng    = (const float*)d_in[10];
    const float* lnb    = (const float*)d_in[11];
    const float* W2     = (const float*)d_in[12];
    const float* b2     = (const float*)d_in[13];
    const float* dng    = (const float*)d_in[14];
    const float* dnb    = (const float*)d_in[15];
    const float* Wout   = (const float*)d_in[16];
    const float* bout   = (const float*)d_in[17];
    float* out = (float*)d_out;
    const int* src = eidx;
    const int* dst = eidx + NE;

    float *px0, *px, *py, *pmid;
    __nv_bfloat16 *paggh, *paggl, *pmidh, *pmidl, *pwh, *pwl, *pwnh, *pwnl, *pxh, *pxl;
    cudaGetSymbolAddress((void**)&px0,   g_x0);
    cudaGetSymbolAddress((void**)&px,    g_x);
    cudaGetSymbolAddress((void**)&py,    g_y);
    cudaGetSymbolAddress((void**)&pmid,  g_mid);
    cudaGetSymbolAddress((void**)&paggh, g_aggh);
    cudaGetSymbolAddress((void**)&paggl, g_aggl);
    cudaGetSymbolAddress((void**)&pmidh, g_midh);
    cudaGetSymbolAddress((void**)&pmidl, g_midl);
    cudaGetSymbolAddress((void**)&pwh,   g_bwh);
    cudaGetSymbolAddress((void**)&pwl,   g_bwl);
    cudaGetSymbolAddress((void**)&pwnh,  g_wnh);
    cudaGetSymbolAddress((void**)&pwnl,  g_wnl);
    cudaGetSymbolAddress((void**)&pxh,   g_xh);
    cudaGetSymbolAddress((void**)&pxl,   g_xl);

    cudaFuncSetAttribute(k_gemm_pipe,
                         cudaFuncAttributeMaxDynamicSharedMemorySize,
                         SMEM_PIPE_BYTES);

    const int MB = (NN + 127) / 128;

    // 1: prep
    k_prep<<<(PREP_Z4 + 255) / 256, 256>>>(Wn, W1, W2, node_x);
    // 2-3: CSR histogram + block scan
    k_hist<<<(NE + 255) / 256, 256>>>(dst);
    k_scan1<<<49, 1024>>>();
    // 4: encoder GEMM (ncu capture window)
    k_gemm_pipe<<<dim3(1, MB), 256, SMEM_PIPE_BYTES>>>(
        pxh, pxl, pwnh, pwnl, bn, nullptr, px0, NN, KPAD, HH,
        nullptr, nullptr, nullptr);
    // 5-7: finish CSR
    k_scan2<<<1, 64>>>();
    k_scan3<<<49, 1024>>>();
    k_scatter<<<(NE + 255) / 256, 256>>>(src, dst, (const float2*)ear);

    const float* xin = px0;
    for (int l = 0; l < 3; l++) {
        k_aggregate<<<592, 256>>>(xin, paggh, paggl, We, be, tt, l);
        k_gemm_pipe<<<dim3(2, MB), 256, SMEM_PIPE_BYTES>>>(
            paggh, paggl,
            pwh + OFF_W1 + l * SZ_W1, pwl + OFF_W1 + l * SZ_W1,
            b1 + l * HB2, nullptr, pmid, NN, HH, HB2,
            nullptr, nullptr, nullptr);
        k_lnrelu256<<<6250, 256>>>(pmid, pmidh, pmidl, lng + l * HB2, lnb + l * HB2);
        const float* png = (l < 2) ? (dng + (l + 1) * HH) : nullptr;
        const float* pnb = (l < 2) ? (dnb + (l + 1) * HH) : nullptr;
        float* yout = (l < 2) ? py : nullptr;
        k_gemm_pipe<<<dim3(1, MB), 256, SMEM_PIPE_BYTES>>>(
            pmidh, pmidl,
            pwh + OFF_W2 + l * SZ_W2, pwl + OFF_W2 + l * SZ_W2,
            b2 + l * HH, (l == 0) ? nullptr : px, px, NN, HB2, HH,
            png, pnb, yout);
        xin = py;
    }
    k_final<<<6250, 256>>>(px, dng, dnb, Wout, bout, out);
}